// round 14
// baseline (speedup 1.0000x reference)
#include <cuda_runtime.h>

// SVConvTranspose2d, round 14: single-wave, ZERO-smem, higher-occupancy
// variant of the champion body.
//
// x:      (4, 16, 128, 128) f32        -- 4 MB, L2-hot
// weight: (16, 16, 5, 5, 128, 128) f32 -- 419 MB DRAM-read once
//                                         (np twin warps dedup in L1)
// bias:   (1, 16, 1, 1) f32
// out:    (4, 16, 128, 128) f32
//
// out[n,o,oh,ow] = bias[o] + sum wt[i,o,kh,kw,h,w] * x[n,i,h,w],
//   h = oh+2-kh (gather), ow = w+kw-2 (scatter into acc window).
//
// Block = 128 thr = (q:32 quads) x (o2:2 outs) x (np:2 batch-pairs).
// Each thread: ALL 16 input channels, 2 batches, 1 out channel ->
// no reduction across threads at all: shuffle-combine + direct store.
// acc[2][8] window over out positions [4q-2,4q+6): tap (kw,j) -> j+kw.
// Hot loop per (kh,i): 5 weight LDG.128 batched FIRST, 2 x LDG.128, 40 FMA.
//
// Grid = 128 rows x 8 o-pairs = 1024 blocks.
// __launch_bounds__(128,8): 64-reg cap (body proven to fit in R8),
// 8 blocks/SM -> 1184 concurrent >= 1024 grid: ONE wave, 32 warps/SM.

#define H_  128
#define W_  128
#define HW  16384

__global__ __launch_bounds__(128, 8)
void svct_kernel(const float* __restrict__ x,
                 const float* __restrict__ wt,
                 const float* __restrict__ bias,
                 float* __restrict__ out)
{
    const int t   = threadIdx.x;
    const int q   = t & 31;              // quad index in row == lane
    const int o2  = (t >> 5) & 1;        // which of the 2 outs
    const int np  = (t >> 6) & 1;        // batch pair: n in {2np, 2np+1}
    const int oh  = blockIdx.x >> 3;     // output row
    const int og  = blockIdx.x & 7;      // o-pair
    const int oc  = og * 2 + o2;         // output channel
    const int n0  = np * 2;

    float acc[2][8];                     // [m][window k]
    #pragma unroll
    for (int m = 0; m < 2; m++)
        #pragma unroll
        for (int k = 0; k < 8; k++)
            acc[m][k] = 0.0f;

    #pragma unroll 1
    for (int kh = 0; kh < 5; kh++) {
        const int h = oh + 2 - kh;
        if ((unsigned)h >= (unsigned)H_) continue;

        #pragma unroll 1
        for (int i = 0; i < 16; i++) {
            // Weight batch FIRST: 5 aligned quads = 5 independent DRAM
            // lines in flight per warp. __ldg so the np twin hits L1.
            const long wrow = ((long)((i * 16 + oc) * 5 + kh) * 5) * HW + (long)h * W_;
            float4 w4[5];
            #pragma unroll
            for (int kw = 0; kw < 5; kw++)
                w4[kw] = __ldg((const float4*)(wt + wrow + (long)kw * HW) + q);

            // Then 2 L2-hot x quads at the same spatial position.
            float4 xq[2];
            #pragma unroll
            for (int m = 0; m < 2; m++)
                xq[m] = __ldg((const float4*)x + (((n0 + m) * 16 + i) * H_ + h) * 32 + q);

            #pragma unroll
            for (int kw = 0; kw < 5; kw++) {
                const float wv[4] = {w4[kw].x, w4[kw].y, w4[kw].z, w4[kw].w};
                #pragma unroll
                for (int m = 0; m < 2; m++) {
                    const float xv[4] = {xq[m].x, xq[m].y, xq[m].z, xq[m].w};
                    #pragma unroll
                    for (int j = 0; j < 4; j++)
                        acc[m][j + kw] = fmaf(wv[j], xv[j], acc[m][j + kw]);
                }
            }
        }
    }

    // cross-lane combine (4 shuffles per m) and direct store -- no smem.
    const bool q0  = (q == 0);
    const bool q31 = (q == 31);
    const float b  = __ldg(bias + oc);

    #pragma unroll
    for (int m = 0; m < 2; m++) {
        float up6 = __shfl_up_sync(0xffffffffu, acc[m][6], 1);
        float up7 = __shfl_up_sync(0xffffffffu, acc[m][7], 1);
        float dn0 = __shfl_down_sync(0xffffffffu, acc[m][0], 1);
        float dn1 = __shfl_down_sync(0xffffffffu, acc[m][1], 1);
        if (q0)  { up6 = 0.0f; up7 = 0.0f; }
        if (q31) { dn0 = 0.0f; dn1 = 0.0f; }

        float4 r;
        r.x = acc[m][2] + up6 + b;
        r.y = acc[m][3] + up7 + b;
        r.z = acc[m][4] + dn0 + b;
        r.w = acc[m][5] + dn1 + b;

        ((float4*)out)[(((n0 + m) * 16 + oc) * H_ + oh) * 32 + q] = r;
    }
}

extern "C" void kernel_launch(void* const* d_in, const int* in_sizes, int n_in,
                              void* d_out, int out_size)
{
    const float* x    = (const float*)d_in[0];
    const float* wt   = (const float*)d_in[1];
    const float* bias = (const float*)d_in[2];
    float*       out  = (float*)d_out;

    svct_kernel<<<1024, 128>>>(x, wt, bias, out);
}